// round 13
// baseline (speedup 1.0000x reference)
#include <cuda_runtime.h>
#include <math.h>

// ---------------- configuration ----------------
#define TPB  128      // threads per block
#define IT   8        // i's per thread (4 packed f32x2 lanes)
#define ITP  (IT/2)
#define JC   128      // j-chunk size (smem tile)
#define MAXN 8192
#define NJC  (MAXN / JC)                  // 64 j-chunks (= barrier columns)
#define NIG  (MAXN / (TPB * IT))          // 8 i-groups (= arrivals per column)
#define NBLK (NJC * NIG)                  // 512 blocks (co-resident @ <=4/SM)
#define NUV  NBLK                         // 512 uv partials
#define P2B  64                           // phase-2 blocks (64*128 = 8192 rows)
#define NSUM 11
#define ABSMASK 0x7FFFFFFF7FFFFFFFULL

// ---------------- device scratch (static, no allocation) ----------------
__device__ float  g_apart[NJC * MAXN];
__device__ float  g_bpart[NJC * MAXN];
__device__ double g_uvpart[NUV];
__device__ double g_red[P2B * NSUM];

// distributed arrival barrier: one counter per j-column, 128B apart
struct PadCnt { unsigned int cnt; unsigned int pad[31]; };
__device__ PadCnt g_cols[NJC];            // zero-initialized; reset by last block
__device__ unsigned int g_bar2 = 0;       // phase-2 ticket (64 arrivals only)

// ---------------- f32x2 helpers ----------------
typedef unsigned long long u64;

__device__ __forceinline__ u64 f2pack(float x) {
    u64 r; asm("mov.b64 %0, {%1, %1};" : "=l"(r) : "f"(x)); return r;
}
__device__ __forceinline__ u64 add2(u64 a, u64 b) {
    u64 r; asm("add.rn.f32x2 %0, %1, %2;" : "=l"(r) : "l"(a), "l"(b)); return r;
}
__device__ __forceinline__ u64 mul2(u64 a, u64 b) {
    u64 r; asm("mul.rn.f32x2 %0, %1, %2;" : "=l"(r) : "l"(a), "l"(b)); return r;
}
__device__ __forceinline__ u64 fma2(u64 a, u64 b, u64 c) {
    u64 r; asm("fma.rn.f32x2 %0, %1, %2, %3;" : "=l"(r) : "l"(a), "l"(b), "l"(c)); return r;
}
__device__ __forceinline__ void unpack2(u64 v, float& lo, float& hi) {
    asm("mov.b64 {%0, %1}, %2;" : "=f"(lo), "=f"(hi) : "l"(v));
}

// ---------------- block reduction (double), 128 threads ----------------
__device__ __forceinline__ double blockReduceSumD(double val) {
    __shared__ double shared[4];
    __syncthreads();
    int lane = threadIdx.x & 31;
    int wid  = threadIdx.x >> 5;
    #pragma unroll
    for (int o = 16; o > 0; o >>= 1)
        val += __shfl_down_sync(0xffffffffu, val, o);
    if (lane == 0) shared[wid] = val;
    __syncthreads();
    if (wid == 0) {
        val = (lane < 4) ? shared[lane] : 0.0;
        #pragma unroll
        for (int o = 2; o > 0; o >>= 1)
            val += __shfl_down_sync(0xffffffffu, val, o);
    }
    return val;  // valid on thread 0
}

// ---------------- single fused persistent kernel ----------------
__global__ __launch_bounds__(TPB, 4) void k_all(const float* __restrict__ a,    // outputs
                                                const float* __restrict__ y,    // labels
                                                const float* __restrict__ b,    // event
                                                const float* __restrict__ w,    // weights
                                                float* __restrict__ out, int n) {
    const int tid = threadIdx.x;
    const int bid = blockIdx.y * gridDim.x + blockIdx.x;

    // ================= PHASE 1: pair compute (IT=8) =================
    __shared__ u64 sna[JC], snb[JC], sw2[JC];
    const int jBase = blockIdx.x * JC;
    sna[tid] = f2pack(-a[jBase + tid]);
    snb[tid] = f2pack(-b[jBase + tid]);
    sw2[tid] = f2pack(w[jBase + tid]);
    __syncthreads();

    const int iBase = blockIdx.y * (TPB * IT);
    u64 ai2[ITP], bi2[ITP], acc_uv[ITP], acc_a[ITP], acc_b[ITP];
    #pragma unroll
    for (int m = 0; m < ITP; m++) {
        int ilo = iBase + (2 * m) * TPB + tid;
        int ihi = iBase + (2 * m + 1) * TPB + tid;
        float alo = a[ilo], ahi = a[ihi];
        float blo = b[ilo], bhi = b[ihi];
        asm("mov.b64 %0, {%1, %2};" : "=l"(ai2[m]) : "f"(alo), "f"(ahi));
        asm("mov.b64 %0, {%1, %2};" : "=l"(bi2[m]) : "f"(blo), "f"(bhi));
        acc_uv[m] = 0ull; acc_a[m] = 0ull; acc_b[m] = 0ull;
    }

    #pragma unroll 2
    for (int j = 0; j < JC; j++) {
        u64 naj = sna[j], nbj = snb[j], wj2 = sw2[j];
        #pragma unroll
        for (int m = 0; m < ITP; m++) {
            u64 da = add2(ai2[m], naj);
            u64 db = add2(bi2[m], nbj);
            da &= ABSMASK;
            db &= ABSMASK;
            u64 t  = mul2(da, wj2);
            acc_a[m]  = add2(acc_a[m], t);
            acc_uv[m] = fma2(t, db, acc_uv[m]);
            acc_b[m]  = fma2(db, wj2, acc_b[m]);
        }
    }

    const int jc = blockIdx.x;
    {
        double s = 0.0;
        #pragma unroll
        for (int m = 0; m < ITP; m++) {
            int ilo = iBase + (2 * m) * TPB + tid;
            int ihi = iBase + (2 * m + 1) * TPB + tid;
            float alo, ahi, blo, bhi, ulo, uhi;
            unpack2(acc_a[m], alo, ahi);
            unpack2(acc_b[m], blo, bhi);
            unpack2(acc_uv[m], ulo, uhi);
            g_apart[jc * n + ilo] = alo;  g_apart[jc * n + ihi] = ahi;
            g_bpart[jc * n + ilo] = blo;  g_bpart[jc * n + ihi] = bhi;
            s += (double)w[ilo] * (double)ulo + (double)w[ihi] * (double)uhi;
        }
        double r = blockReduceSumD(s);
        if (tid == 0) g_uvpart[bid] = r;
    }

    // ================= DISTRIBUTED GRID BARRIER =================
    __syncthreads();
    __threadfence();
    if (tid == 0) atomicAdd(&g_cols[blockIdx.x].cnt, 1u);

    if (bid >= P2B) return;     // only blocks with blockIdx.y==0 continue

    // threads 0..63 each spin on their own column counter (NIG=8 arrivals each)
    if (tid < NJC) {
        while (*((volatile unsigned int*)&g_cols[tid].cnt) < (unsigned int)NIG)
            __nanosleep(64);
    }
    __syncthreads();
    __threadfence();            // acquire: see all blocks' scratch stores

    // ================= PHASE 2: row reduce (one row per thread) =================
    const int lane = tid & 31;
    const int wid  = tid >> 5;
    const int i    = bid * TPB + tid;

    float a1 = 0.f, b1 = 0.f;
    #pragma unroll 8
    for (int c = 0; c < NJC; c++) {
        a1 += g_apart[c * n + i];
        b1 += g_bpart[c * n + i];
    }

    const float xi = a[i], yi = y[i], ei = b[i], wi = w[i];
    const float sp = fmaxf(xi, 0.f) + log1pf(expf(-fabsf(xi)));  // softplus

    const double ad = (double)a1, bd = (double)b1, wd = (double)wi;
    double v[NSUM];
    v[0]  = ad * wd;
    v[1]  = bd * wd;
    v[2]  = ad * bd * wd;
    v[3]  = ad * ad * wd;
    v[4]  = bd * bd * wd;
    v[5]  = wd;
    v[6]  = (double)((sp - xi * yi) * wi);
    v[7]  = (double)xi * wd;
    v[8]  = (double)xi * (double)xi * wd;
    v[9]  = (double)ei * wd;
    v[10] = (double)ei * (double)ei * wd;

    #pragma unroll
    for (int o = 16; o > 0; o >>= 1) {
        #pragma unroll
        for (int c = 0; c < NSUM; c++)
            v[c] += __shfl_down_sync(0xffffffffu, v[c], o);
    }

    __shared__ double warpsums[TPB / 32][NSUM];
    if (lane == 0) {
        #pragma unroll
        for (int c = 0; c < NSUM; c++) warpsums[wid][c] = v[c];
    }
    __syncthreads();

    if (tid < NSUM) {
        double s = 0.0;
        #pragma unroll
        for (int w2 = 0; w2 < TPB / 32; w2++) s += warpsums[w2][tid];
        g_red[bid * NSUM + tid] = s;
    }

    // ---- ticket among the P2B=64 phase-2 blocks ----
    __shared__ bool amLast;
    __syncthreads();
    __threadfence();
    if (tid == 0) {
        unsigned int ticket = atomicAdd(&g_bar2, 1u);
        amLast = (ticket == P2B - 1);
    }
    __syncthreads();
    if (!amLast) return;
    __threadfence();

    // ================= FINAL COMBINE (one block) =================
    __shared__ double sres[NSUM + 1];

    double s = 0.0;
    #pragma unroll
    for (int k = 0; k < NUV / TPB; k++) s += g_uvpart[k * TPB + tid];
    double r = blockReduceSumD(s);
    if (tid == 0) sres[0] = r;

    for (int c = wid; c < NSUM; c += TPB / 32) {
        double vv = g_red[lane * NSUM + c] + g_red[(lane + 32) * NSUM + c];
        #pragma unroll
        for (int o = 16; o > 0; o >>= 1)
            vv += __shfl_down_sync(0xffffffffu, vv, o);
        if (lane == 0) sres[1 + c] = vv;
    }
    __syncthreads();

    if (tid == 0) {
        const double Suv = sres[0];
        const double Sa  = sres[1];
        const double Sb  = sres[2];
        const double Sab = sres[3];
        const double Saa = sres[4];
        const double Sbb = sres[5];
        const double W   = sres[6];
        const double Sbce= sres[7];
        const double Saw = sres[8];
        const double Sa2 = sres[9];
        const double Sew = sres[10];
        const double Se2 = sres[11];

        const double W2 = W * W, W3 = W2 * W, W4 = W2 * W2;

        double num  = Suv / W2 - 2.0 * Sab / W3 + (Sa * Sb) / W4;
        double denA = 2.0 * (W * Sa2 - Saw * Saw) / W2 - 2.0 * Saa / W3 + (Sa * Sa) / W4;
        double denB = 2.0 * (W * Se2 - Sew * Sew) / W2 - 2.0 * Sbb / W3 + (Sb * Sb) / W4;

        double disco = num / sqrt(denA * denB);
        double bce   = Sbce / (double)n;

        out[0] = (float)bce;
        out[1] = (float)disco;
        out[2] = (float)(bce + 0.1 * disco);

        g_bar2 = 0u;
    }
    // last block resets the 64 column counters for the next graph replay.
    if (amLast && tid < NJC) g_cols[tid].cnt = 0u;
}

// ---------------- launch ----------------
extern "C" void kernel_launch(void* const* d_in, const int* in_sizes, int n_in,
                              void* d_out, int out_size) {
    const float* outputs = (const float*)d_in[0];
    const float* labels  = (const float*)d_in[1];
    const float* event   = (const float*)d_in[2];
    const float* weights = (const float*)d_in[3];
    float* out = (float*)d_out;
    const int n = in_sizes[0];   // 8192

    dim3 g(NJC, NIG);   // (64, 8) = 512 blocks, all co-resident
    k_all<<<g, TPB>>>(outputs, labels, event, weights, out, n);
}

// round 14
// speedup vs baseline: 1.1165x; 1.1165x over previous
#include <cuda_runtime.h>
#include <math.h>

// ---------------- configuration ----------------
#define TPB  128      // threads per block
#define IT   4        // i's per thread (2 packed f32x2 lanes)
#define ITP  (IT/2)
#define JC   128      // j-chunk size (smem tile)
#define MAXN 8192
#define NJC  (MAXN / JC)                  // 64 j-chunks (= barrier columns)
#define NIG  (MAXN / (TPB * IT))          // 16 i-groups (= arrivals per column)
#define NBLK (NJC * NIG)                  // 1024 blocks (all co-resident @ 8/SM)
#define NUV  NBLK                         // 1024 uv partials
#define P2B  64                           // phase-2 blocks (64*128 = 8192 rows)
#define NSUM 11
#define ABSMASK 0x7FFFFFFF7FFFFFFFULL

// ---------------- device scratch (static, no allocation) ----------------
// transposed + interleaved: row i holds 64 float2{alpha_c, beta_c} contiguous
__device__ float2 g_part[MAXN * NJC];      // 4 MB
__device__ double g_uvpart[NUV];
__device__ double g_red[P2B * NSUM];

// distributed arrival barrier: one counter per j-column, 128B apart
struct PadCnt { unsigned int cnt; unsigned int pad[31]; };
__device__ PadCnt g_cols[NJC];            // zero-initialized; reset by last block
__device__ unsigned int g_bar2 = 0;       // phase-2 ticket (64 arrivals only)

// ---------------- f32x2 helpers ----------------
typedef unsigned long long u64;

__device__ __forceinline__ u64 f2pack(float x) {
    u64 r; asm("mov.b64 %0, {%1, %1};" : "=l"(r) : "f"(x)); return r;
}
__device__ __forceinline__ u64 add2(u64 a, u64 b) {
    u64 r; asm("add.rn.f32x2 %0, %1, %2;" : "=l"(r) : "l"(a), "l"(b)); return r;
}
__device__ __forceinline__ u64 mul2(u64 a, u64 b) {
    u64 r; asm("mul.rn.f32x2 %0, %1, %2;" : "=l"(r) : "l"(a), "l"(b)); return r;
}
__device__ __forceinline__ u64 fma2(u64 a, u64 b, u64 c) {
    u64 r; asm("fma.rn.f32x2 %0, %1, %2, %3;" : "=l"(r) : "l"(a), "l"(b), "l"(c)); return r;
}
__device__ __forceinline__ void unpack2(u64 v, float& lo, float& hi) {
    asm("mov.b64 {%0, %1}, %2;" : "=f"(lo), "=f"(hi) : "l"(v));
}

// ---------------- block reduction (double), 128 threads ----------------
__device__ __forceinline__ double blockReduceSumD(double val) {
    __shared__ double shared[4];
    __syncthreads();
    int lane = threadIdx.x & 31;
    int wid  = threadIdx.x >> 5;
    #pragma unroll
    for (int o = 16; o > 0; o >>= 1)
        val += __shfl_down_sync(0xffffffffu, val, o);
    if (lane == 0) shared[wid] = val;
    __syncthreads();
    if (wid == 0) {
        val = (lane < 4) ? shared[lane] : 0.0;
        #pragma unroll
        for (int o = 2; o > 0; o >>= 1)
            val += __shfl_down_sync(0xffffffffu, val, o);
    }
    return val;  // valid on thread 0
}

// ---------------- single fused persistent kernel ----------------
__global__ __launch_bounds__(TPB, 8) void k_all(const float* __restrict__ a,    // outputs
                                                const float* __restrict__ y,    // labels
                                                const float* __restrict__ b,    // event
                                                const float* __restrict__ w,    // weights
                                                float* __restrict__ out, int n) {
    const int tid = threadIdx.x;
    const int bid = blockIdx.y * gridDim.x + blockIdx.x;

    // ================= PHASE 1: pair compute (R12 math) =================
    __shared__ u64 sna[JC], snb[JC], sw2[JC];
    const int jBase = blockIdx.x * JC;
    sna[tid] = f2pack(-a[jBase + tid]);
    snb[tid] = f2pack(-b[jBase + tid]);
    sw2[tid] = f2pack(w[jBase + tid]);
    __syncthreads();

    const int iBase = blockIdx.y * (TPB * IT);
    u64 ai2[ITP], bi2[ITP], acc_uv[ITP], acc_a[ITP], acc_b[ITP];
    #pragma unroll
    for (int m = 0; m < ITP; m++) {
        int ilo = iBase + (2 * m) * TPB + tid;
        int ihi = iBase + (2 * m + 1) * TPB + tid;
        float alo = a[ilo], ahi = a[ihi];
        float blo = b[ilo], bhi = b[ihi];
        asm("mov.b64 %0, {%1, %2};" : "=l"(ai2[m]) : "f"(alo), "f"(ahi));
        asm("mov.b64 %0, {%1, %2};" : "=l"(bi2[m]) : "f"(blo), "f"(bhi));
        acc_uv[m] = 0ull; acc_a[m] = 0ull; acc_b[m] = 0ull;
    }

    #pragma unroll 4
    for (int j = 0; j < JC; j++) {
        u64 naj = sna[j], nbj = snb[j], wj2 = sw2[j];
        #pragma unroll
        for (int m = 0; m < ITP; m++) {
            u64 da = add2(ai2[m], naj);
            u64 db = add2(bi2[m], nbj);
            da &= ABSMASK;
            db &= ABSMASK;
            u64 t  = mul2(da, wj2);
            acc_a[m]  = add2(acc_a[m], t);
            acc_uv[m] = fma2(t, db, acc_uv[m]);
            acc_b[m]  = fma2(db, wj2, acc_b[m]);
        }
    }

    const int jc = blockIdx.x;
    {
        double s = 0.0;
        #pragma unroll
        for (int m = 0; m < ITP; m++) {
            int ilo = iBase + (2 * m) * TPB + tid;
            int ihi = iBase + (2 * m + 1) * TPB + tid;
            float alo, ahi, blo, bhi, ulo, uhi;
            unpack2(acc_a[m], alo, ahi);
            unpack2(acc_b[m], blo, bhi);
            unpack2(acc_uv[m], ulo, uhi);
            g_part[ilo * NJC + jc] = make_float2(alo, blo);
            g_part[ihi * NJC + jc] = make_float2(ahi, bhi);
            s += (double)w[ilo] * (double)ulo + (double)w[ihi] * (double)uhi;
        }
        double r = blockReduceSumD(s);
        if (tid == 0) g_uvpart[bid] = r;
    }

    // ================= DISTRIBUTED GRID BARRIER =================
    __syncthreads();
    __threadfence();
    if (tid == 0) atomicAdd(&g_cols[blockIdx.x].cnt, 1u);

    if (bid >= P2B) return;     // only blocks with blockIdx.y==0 continue

    // threads 0..63 each spin on their own column counter (NIG arrivals each)
    if (tid < NJC) {
        while (*((volatile unsigned int*)&g_cols[tid].cnt) < (unsigned int)NIG)
            __nanosleep(64);
    }
    __syncthreads();
    __threadfence();            // acquire: see all blocks' scratch stores

    // ================= PHASE 2: row reduce (one row per thread, vectorized) ====
    const int lane = tid & 31;
    const int wid  = tid >> 5;
    const int i    = bid * TPB + tid;

    // 32 contiguous LDG.128 over the interleaved row (64 float2 = 512B)
    float a1 = 0.f, b1 = 0.f;
    const float4* p = reinterpret_cast<const float4*>(&g_part[i * NJC]);
    #pragma unroll
    for (int k = 0; k < NJC / 2; k++) {
        float4 v4 = p[k];
        a1 += v4.x + v4.z;
        b1 += v4.y + v4.w;
    }

    const float xi = a[i], yi = y[i], ei = b[i], wi = w[i];
    const float sp = fmaxf(xi, 0.f) + log1pf(expf(-fabsf(xi)));  // softplus

    const double ad = (double)a1, bd = (double)b1, wd = (double)wi;
    double v[NSUM];
    v[0]  = ad * wd;
    v[1]  = bd * wd;
    v[2]  = ad * bd * wd;
    v[3]  = ad * ad * wd;
    v[4]  = bd * bd * wd;
    v[5]  = wd;
    v[6]  = (double)((sp - xi * yi) * wi);
    v[7]  = (double)xi * wd;
    v[8]  = (double)xi * (double)xi * wd;
    v[9]  = (double)ei * wd;
    v[10] = (double)ei * (double)ei * wd;

    #pragma unroll
    for (int o = 16; o > 0; o >>= 1) {
        #pragma unroll
        for (int c = 0; c < NSUM; c++)
            v[c] += __shfl_down_sync(0xffffffffu, v[c], o);
    }

    __shared__ double warpsums[TPB / 32][NSUM];
    if (lane == 0) {
        #pragma unroll
        for (int c = 0; c < NSUM; c++) warpsums[wid][c] = v[c];
    }
    __syncthreads();

    if (tid < NSUM) {
        double s = 0.0;
        #pragma unroll
        for (int w2 = 0; w2 < TPB / 32; w2++) s += warpsums[w2][tid];
        g_red[bid * NSUM + tid] = s;
    }

    // ---- ticket among the P2B=64 phase-2 blocks ----
    __shared__ bool amLast;
    __syncthreads();
    __threadfence();
    if (tid == 0) {
        unsigned int ticket = atomicAdd(&g_bar2, 1u);
        amLast = (ticket == P2B - 1);
    }
    __syncthreads();
    if (!amLast) return;
    __threadfence();

    // ================= FINAL COMBINE (one block) =================
    __shared__ double sres[NSUM + 1];

    double s = 0.0;
    #pragma unroll
    for (int k = 0; k < NUV / TPB; k++) s += g_uvpart[k * TPB + tid];
    double r = blockReduceSumD(s);
    if (tid == 0) sres[0] = r;

    for (int c = wid; c < NSUM; c += TPB / 32) {
        double vv = g_red[lane * NSUM + c] + g_red[(lane + 32) * NSUM + c];
        #pragma unroll
        for (int o = 16; o > 0; o >>= 1)
            vv += __shfl_down_sync(0xffffffffu, vv, o);
        if (lane == 0) sres[1 + c] = vv;
    }
    __syncthreads();

    if (tid == 0) {
        const double Suv = sres[0];
        const double Sa  = sres[1];
        const double Sb  = sres[2];
        const double Sab = sres[3];
        const double Saa = sres[4];
        const double Sbb = sres[5];
        const double W   = sres[6];
        const double Sbce= sres[7];
        const double Saw = sres[8];
        const double Sa2 = sres[9];
        const double Sew = sres[10];
        const double Se2 = sres[11];

        const double W2 = W * W, W3 = W2 * W, W4 = W2 * W2;

        double num  = Suv / W2 - 2.0 * Sab / W3 + (Sa * Sb) / W4;
        double denA = 2.0 * (W * Sa2 - Saw * Saw) / W2 - 2.0 * Saa / W3 + (Sa * Sa) / W4;
        double denB = 2.0 * (W * Se2 - Sew * Sew) / W2 - 2.0 * Sbb / W3 + (Sb * Sb) / W4;

        double disco = num / sqrt(denA * denB);
        double bce   = Sbce / (double)n;

        out[0] = (float)bce;
        out[1] = (float)disco;
        out[2] = (float)(bce + 0.1 * disco);

        g_bar2 = 0u;
    }
    // last block resets the 64 column counters for the next graph replay.
    if (amLast && tid < NJC) g_cols[tid].cnt = 0u;
}

// ---------------- launch ----------------
extern "C" void kernel_launch(void* const* d_in, const int* in_sizes, int n_in,
                              void* d_out, int out_size) {
    const float* outputs = (const float*)d_in[0];
    const float* labels  = (const float*)d_in[1];
    const float* event   = (const float*)d_in[2];
    const float* weights = (const float*)d_in[3];
    float* out = (float*)d_out;
    const int n = in_sizes[0];   // 8192

    dim3 g(NJC, NIG);   // (64, 16) = 1024 blocks, all co-resident
    k_all<<<g, TPB>>>(outputs, labels, event, weights, out, n);
}